// round 12
// baseline (speedup 1.0000x reference)
#include <cuda_runtime.h>
#include <cuda_bf16.h>
#include <math.h>
#include <stdint.h>

#define NSTMT 100000
#define NFUNC 50000
#define NTOT  150000
#define TT 16
#define CC 128
#define HH 8
#define DD 16
#define NLAYER 2
#define EE 200000
#define KPAD 136          // bf16 units per smem row
#define NMAT 22
#define WTU 8192          // u32 per transposed-bf16 matrix (128 n x 64 k-pairs)

// ---------------- scratch (static device globals; no allocation) ----------------
__device__ float g_XA[(size_t)NTOT * CC];
__device__ float g_XB[(size_t)NTOT * CC];
__device__ float g_Q [(size_t)NTOT * CC];
__device__ float g_AGG[(size_t)NTOT * CC];
__device__ float g_KR0[(size_t)NSTMT * CC];
__device__ float g_VR0[(size_t)NSTMT * CC];
__device__ float g_KR1[(size_t)NSTMT * CC];
__device__ float g_VR1[(size_t)NSTMT * CC];
__device__ float g_KR2[(size_t)NFUNC * CC];
__device__ float g_VR2[(size_t)NFUNC * CC];
__device__ float g_LG[(size_t)3 * EE * HH];
__device__ float g_M [(size_t)3 * NSTMT * HH];
__device__ float g_S [(size_t)3 * NSTMT * HH];
// combined rel-folded weights/biases
__device__ float g_WK[(size_t)NLAYER * 3 * CC * CC];
__device__ float g_WV[(size_t)NLAYER * 3 * CC * CC];
__device__ float g_BK[(size_t)NLAYER * 3 * CC];
__device__ float g_BV[(size_t)NLAYER * 3 * CC];
// transposed bf16 hi/lo weights: [mat][n][64 u32]
__device__ uint32_t g_WTH[(size_t)NMAT * WTU];
__device__ uint32_t g_WTL[(size_t)NMAT * WTU];

// ---------------- helpers ----------------
__device__ __forceinline__ void atomicMaxF(float* addr, float v) {
    if (v >= 0.0f) atomicMax((int*)addr, __float_as_int(v));
    else           atomicMin((unsigned int*)addr, __float_as_uint(v));
}

__device__ __forceinline__ void redAdd4(float* p, float4 v) {
    asm volatile("red.global.add.v4.f32 [%0], {%1, %2, %3, %4};"
                 :: "l"(p), "f"(v.x), "f"(v.y), "f"(v.z), "f"(v.w) : "memory");
}

__device__ __forceinline__ float gelu1(float v) {
    float c = 0.7978845608028654f * (v + 0.044715f * v * v * v);
    return 0.5f * v * (1.0f + tanhf(c));
}

__device__ __forceinline__ uint32_t bf2pack(float a, float b) {
    __nv_bfloat162 t = __floats2bfloat162_rn(a, b);
    return *reinterpret_cast<uint32_t*>(&t);
}

__device__ __forceinline__ void mma16816(float* c, uint32_t a0, uint32_t a1, uint32_t a2, uint32_t a3,
                                         uint32_t b0, uint32_t b1) {
    asm volatile(
        "mma.sync.aligned.m16n8k16.row.col.f32.bf16.bf16.f32 "
        "{%0,%1,%2,%3}, {%4,%5,%6,%7}, {%8,%9}, {%0,%1,%2,%3};"
        : "+f"(c[0]), "+f"(c[1]), "+f"(c[2]), "+f"(c[3])
        : "r"(a0), "r"(a1), "r"(a2), "r"(a3), "r"(b0), "r"(b1));
}

// ---------------- weight combine: W' = W @ blockdiag(rel) ----------------
__global__ void combine_kernel(const float* __restrict__ kw, const float* __restrict__ kb,
                               const float* __restrict__ vw, const float* __restrict__ vb,
                               const float* __restrict__ a_rel, const float* __restrict__ m_rel,
                               float* __restrict__ WK, float* __restrict__ BK,
                               float* __restrict__ WV, float* __restrict__ BV)
{
    int b = blockIdx.x;                    // l*6 + r*2 + kind
    int l = b / 6, rr = (b % 6) >> 1, kind = b & 1;
    int st = (rr == 2) ? 1 : 0;
    const float* Wsrc = (kind ? vw : kw) + (size_t)(l * 2 + st) * CC * CC;
    const float* bsrc = (kind ? vb : kb) + (size_t)(l * 2 + st) * CC;
    const float* rel  = (kind ? m_rel : a_rel) + (size_t)(l * 3 + rr) * HH * DD * DD;
    float* Wdst = (kind ? WV : WK) + (size_t)(l * 3 + rr) * CC * CC;
    float* bdst = (kind ? BV : BK) + (size_t)(l * 3 + rr) * CC;

    __shared__ float srel[HH * DD * DD];
    for (int i = threadIdx.x; i < HH * DD * DD; i += blockDim.x) srel[i] = rel[i];
    __syncthreads();

    for (int idx = threadIdx.x; idx < CC * CC; idx += blockDim.x) {
        int j = idx >> 7, c = idx & 127;
        int h = c >> 4, e = c & 15;
        float s = 0.f;
#pragma unroll
        for (int d = 0; d < DD; d++)
            s = fmaf(__ldg(Wsrc + j * CC + h * DD + d), srel[h * DD * DD + d * DD + e], s);
        Wdst[idx] = s;
    }
    if (threadIdx.x < CC) {
        int c = threadIdx.x, h = c >> 4, e = c & 15;
        float s = 0.f;
#pragma unroll
        for (int d = 0; d < DD; d++)
            s = fmaf(__ldg(bsrc + h * DD + d), srel[h * DD * DD + d * DD + e], s);
        bdst[c] = s;
    }
}

// ---------------- one-time: W -> transposed bf16 hi/lo [n][64 u32] ----------------
struct WSrc { const float* w[NMAT]; };

__global__ void wconv_kernel(WSrc s, uint32_t* __restrict__ WTH, uint32_t* __restrict__ WTL)
{
    int mat = blockIdx.x;
    const float* W = s.w[mat];
    int tid = threadIdx.x;
    int n = tid >> 1;
    int k0 = (tid & 1) * 32;
    uint32_t* dh = WTH + (size_t)mat * WTU + n * 64;
    uint32_t* dl = WTL + (size_t)mat * WTU + n * 64;
#pragma unroll 4
    for (int j = 0; j < 32; j++) {
        int kp = k0 + j;
        float w0 = __ldg(W + (size_t)(2 * kp) * CC + n);
        float w1 = __ldg(W + (size_t)(2 * kp + 1) * CC + n);
        float h0 = __bfloat162float(__float2bfloat16_rn(w0));
        float h1 = __bfloat162float(__float2bfloat16_rn(w1));
        dh[kp] = bf2pack(h0, h1);
        dl[kp] = bf2pack(w0 - h0, w1 - h1);
    }
}

// ---------------- encoder: gather + mean + relu ----------------
__global__ void encode_kernel(const int* __restrict__ tok, const float* __restrict__ emb,
                              float* __restrict__ out, int n)
{
    int node = blockIdx.x * (blockDim.x >> 5) + (threadIdx.x >> 5);
    int lane = threadIdx.x & 31;
    if (node >= n) return;
    const int* tk = tok + (size_t)node * TT;
    float4 acc = make_float4(0.f, 0.f, 0.f, 0.f);
#pragma unroll
    for (int t = 0; t < TT; t++) {
        int id = __ldg(tk + t);
        float4 v = __ldg((const float4*)(emb + (size_t)id * CC) + lane);
        acc.x += v.x; acc.y += v.y; acc.z += v.z; acc.w += v.w;
    }
    const float s = 1.0f / TT;
    acc.x = fmaxf(acc.x * s, 0.f); acc.y = fmaxf(acc.y * s, 0.f);
    acc.z = fmaxf(acc.z * s, 0.f); acc.w = fmaxf(acc.w * s, 0.f);
    ((float4*)(out + (size_t)node * CC))[lane] = acc;
}

// ================= HMMA GEMM core (hi/lo split bf16; W pre-converted) =================
// 512 threads = 16 warps in 4x4 grid; each warp owns 32 rows x 32 cols.
#define GT 512
#define SMEM_GM (4 * 128 * KPAD * 2)

__device__ __forceinline__ void load_W(const uint32_t* __restrict__ WTHm,
                                       const uint32_t* __restrict__ WTLm,
                                       uint32_t* WH, uint32_t* WL, int tid)
{
#pragma unroll
    for (int i = 0; i < 4; i++) {
        int u4 = tid + i * GT;            // 0..2047
        int n = u4 >> 4, q = u4 & 15;
        uint4 h = __ldg((const uint4*)WTHm + u4);
        uint4 l = __ldg((const uint4*)WTLm + u4);
        *(uint4*)(WH + n * (KPAD / 2) + q * 4) = h;
        *(uint4*)(WL + n * (KPAD / 2) + q * 4) = l;
    }
}

__device__ __forceinline__ void convert_A(const float* __restrict__ A, uint32_t* AH, uint32_t* AL,
                                          int r0, int M, int tid, bool dogelu)
{
#pragma unroll
    for (int i = 0; i < 4; i++) {
        int c = tid + i * GT;
        int r = c >> 4, kc = c & 15;
        float x[8];
        if (r0 + r < M) {
            const float4* ap = (const float4*)(A + (size_t)(r0 + r) * CC + kc * 8);
            float4 v0 = __ldg(ap), v1 = __ldg(ap + 1);
            x[0] = v0.x; x[1] = v0.y; x[2] = v0.z; x[3] = v0.w;
            x[4] = v1.x; x[5] = v1.y; x[6] = v1.z; x[7] = v1.w;
            if (dogelu) {
#pragma unroll
                for (int j = 0; j < 8; j++) x[j] = gelu1(x[j]);
            }
        } else {
#pragma unroll
            for (int j = 0; j < 8; j++) x[j] = 0.f;
        }
        int base = r * (KPAD / 2) + kc * 4;
#pragma unroll
        for (int p = 0; p < 4; p++) {
            float a0 = x[2 * p], a1 = x[2 * p + 1];
            float h0 = __bfloat162float(__float2bfloat16_rn(a0));
            float h1 = __bfloat162float(__float2bfloat16_rn(a1));
            AH[base + p] = bf2pack(h0, h1);
            AL[base + p] = bf2pack(a0 - h0, a1 - h1);
        }
    }
}

// 3-pass split MMA: cfr += Ahi*Whi + Ahi*Wlo + Alo*Whi  (warp tile 32x32)
__device__ __forceinline__ void mma_core(const uint32_t* AH, const uint32_t* AL,
                                         const uint32_t* WH, const uint32_t* WL,
                                         int wm, int wn, int gr, int qp, float cfr[2][4][4])
{
#pragma unroll
    for (int i = 0; i < 2; i++)
#pragma unroll
        for (int j = 0; j < 4; j++)
#pragma unroll
            for (int q = 0; q < 4; q++) cfr[i][j][q] = 0.f;
#pragma unroll
    for (int p = 0; p < 3; p++) {
        const uint32_t* As = (p < 2) ? AH : AL;
        const uint32_t* Ws = (p == 1) ? WL : WH;
#pragma unroll
        for (int k16 = 0; k16 < 8; k16++) {
            int kb = k16 * 8 + qp;
            uint32_t b[4][2];
#pragma unroll
            for (int nt = 0; nt < 4; nt++) {
                int n = wn + nt * 8 + gr;
                b[nt][0] = Ws[n * (KPAD / 2) + kb];
                b[nt][1] = Ws[n * (KPAD / 2) + kb + 4];
            }
#pragma unroll
            for (int mt = 0; mt < 2; mt++) {
                int r = wm + mt * 16 + gr;
                uint32_t a0 = As[r * (KPAD / 2) + kb];
                uint32_t a1 = As[(r + 8) * (KPAD / 2) + kb];
                uint32_t a2 = As[r * (KPAD / 2) + kb + 4];
                uint32_t a3 = As[(r + 8) * (KPAD / 2) + kb + 4];
#pragma unroll
                for (int nt = 0; nt < 4; nt++)
                    mma16816(cfr[mt][nt], a0, a1, a2, a3, b[nt][0], b[nt][1]);
            }
        }
    }
}

// ---------------- single-output GEMM (encoder / out-proj with epilogue) ----------------
__global__ __launch_bounds__(GT) void gemm_mma_kernel(
    const float* __restrict__ A, const uint32_t* __restrict__ WTH, const uint32_t* __restrict__ WTL,
    int mat, const float* __restrict__ bias, float* __restrict__ C, int M, int flags,
    const float* __restrict__ Xg, const float* __restrict__ skipp)
{
    extern __shared__ __align__(16) char smem[];
    uint32_t* AH = (uint32_t*)smem;
    uint32_t* AL = AH + 128 * (KPAD / 2);
    uint32_t* WH = AL + 128 * (KPAD / 2);
    uint32_t* WL = WH + 128 * (KPAD / 2);
    const int tid = threadIdx.x;
    const int r0 = blockIdx.x * 128;

    convert_A(A, AH, AL, r0, M, tid, (flags & 2) != 0);
    load_W(WTH + (size_t)mat * WTU, WTL + (size_t)mat * WTU, WH, WL, tid);
    __syncthreads();

    const int w = tid >> 5, lane = tid & 31;
    const int wm = (w & 3) * 32, wn = (w >> 2) * 32;
    const int gr = lane >> 2, qp = lane & 3;

    float cfr[2][4][4];
    mma_core(AH, AL, WH, WL, wm, wn, gr, qp, cfr);

    float g = 0.f;
    if (Xg) g = 1.0f / (1.0f + __expf(-__ldg(skipp)));
#pragma unroll
    for (int mt = 0; mt < 2; mt++) {
#pragma unroll
        for (int half = 0; half < 2; half++) {
            int row = r0 + wm + mt * 16 + gr + half * 8;
            if (row >= M) continue;
#pragma unroll
            for (int nt = 0; nt < 4; nt++) {
                int j = wn + nt * 8 + qp * 2;
                float o0 = cfr[mt][nt][half * 2 + 0] + __ldg(bias + j);
                float o1 = cfr[mt][nt][half * 2 + 1] + __ldg(bias + j + 1);
                if (flags & 1) { o0 = fmaxf(o0, 0.f); o1 = fmaxf(o1, 0.f); }
                if (Xg) {
                    const float2 xv = __ldg((const float2*)(Xg + (size_t)row * CC + j));
                    o0 = g * o0 + (1.f - g) * xv.x;
                    o1 = g * o1 + (1.f - g) * xv.y;
                }
                *(float2*)(C + (size_t)row * CC + j) = make_float2(o0, o1);
            }
        }
    }
}

// ---------------- multi-output GEMM: A resident, loop over weight sets ----------
struct MOuts {
    int mat[5];
    const float* B[5];
    float*       C[5];
};

__global__ __launch_bounds__(GT) void gemm_mma_multi_kernel(
    const float* __restrict__ A, const uint32_t* __restrict__ WTH, const uint32_t* __restrict__ WTL,
    int M, int nw, MOuts o)
{
    extern __shared__ __align__(16) char smem[];
    uint32_t* AH = (uint32_t*)smem;
    uint32_t* AL = AH + 128 * (KPAD / 2);
    uint32_t* WH = AL + 128 * (KPAD / 2);
    uint32_t* WL = WH + 128 * (KPAD / 2);
    const int tid = threadIdx.x;
    const int r0 = blockIdx.x * 128;

    convert_A(A, AH, AL, r0, M, tid, false);

    const int w = tid >> 5, lane = tid & 31;
    const int wm = (w & 3) * 32, wn = (w >> 2) * 32;
    const int gr = lane >> 2, qp = lane & 3;

    for (int s = 0; s < nw; s++) {
        __syncthreads();               // A stores visible (s=0); prior MMA consumers done (s>0)
        load_W(WTH + (size_t)o.mat[s] * WTU, WTL + (size_t)o.mat[s] * WTU, WH, WL, tid);
        __syncthreads();

        float cfr[2][4][4];
        mma_core(AH, AL, WH, WL, wm, wn, gr, qp, cfr);

        const float* bias = o.B[s];
        float* C = o.C[s];
#pragma unroll
        for (int mt = 0; mt < 2; mt++) {
#pragma unroll
            for (int half = 0; half < 2; half++) {
                int row = r0 + wm + mt * 16 + gr + half * 8;
                if (row >= M) continue;
#pragma unroll
                for (int nt = 0; nt < 4; nt++) {
                    int j = wn + nt * 8 + qp * 2;
                    float o0 = cfr[mt][nt][half * 2 + 0] + __ldg(bias + j);
                    float o1 = cfr[mt][nt][half * 2 + 1] + __ldg(bias + j + 1);
                    *(float2*)(C + (size_t)row * CC + j) = make_float2(o0, o1);
                }
            }
        }
    }
}

// ================= edge phase (3 relations batched) =================
struct EdgeCtx {
    const int* src[3]; const int* dst[3];
    const float* Qd[3]; const float* KR[3]; const float* VR[3];
    const float* prel[3];
    float* LG[3]; float* Mx[3]; float* Sm[3]; float* AGG[3];
};

__global__ void logits3_kernel(EdgeCtx c, int nE)
{
    int e = blockIdx.x * (blockDim.x >> 5) + (threadIdx.x >> 5);
    if (e >= 3 * nE) return;
    int r = e / nE, ei = e - r * nE;
    int lane = threadIdx.x & 31;
    int s = __ldg(c.src[r] + ei), d = __ldg(c.dst[r] + ei);
    float4 q = __ldg((const float4*)(c.Qd[r] + (size_t)d * CC) + lane);
    float4 k = __ldg((const float4*)(c.KR[r] + (size_t)s * CC) + lane);
    float p = q.x * k.x + q.y * k.y + q.z * k.z + q.w * k.w;
    p += __shfl_xor_sync(0xffffffffu, p, 1);
    p += __shfl_xor_sync(0xffffffffu, p, 2);
    if ((lane & 3) == 0) {
        int h = lane >> 2;
        float lg = p * __ldg(c.prel[r] + h) * 0.25f;
        c.LG[r][(size_t)ei * HH + h] = lg;
        atomicMaxF(c.Mx[r] + (size_t)d * HH + h, lg);
    }
}

__global__ void expsum3_kernel(EdgeCtx c, int nE)
{
    int i = blockIdx.x * blockDim.x + threadIdx.x;
    int per = nE * HH;
    if (i >= 3 * per) return;
    int r = i / per, rem = i - r * per;
    int e = rem >> 3, h = rem & 7;
    int d = __ldg(c.dst[r] + e);
    float ev = __expf(c.LG[r][rem] - c.Mx[r][(size_t)d * HH + h]);
    c.LG[r][rem] = ev;
    atomicAdd(c.Sm[r] + (size_t)d * HH + h, ev);
}

__global__ void scatter3_kernel(EdgeCtx c, int nE)
{
    int e = blockIdx.x * (blockDim.x >> 5) + (threadIdx.x >> 5);
    if (e >= 3 * nE) return;
    int r = e / nE, ei = e - r * nE;
    int lane = threadIdx.x & 31;
    int h = lane >> 2;
    int s = __ldg(c.src[r] + ei), d = __ldg(c.dst[r] + ei);
    float a = __ldg(c.LG[r] + (size_t)ei * HH + h) /
              (__ldg(c.Sm[r] + (size_t)d * HH + h) + 1e-16f);
    float4 v = __ldg((const float4*)(c.VR[r] + (size_t)s * CC) + lane);
    redAdd4((float*)((float4*)(c.AGG[r] + (size_t)d * CC) + lane),
            make_float4(v.x * a, v.y * a, v.z * a, v.w * a));
}

__global__ void init_ms_kernel(float* __restrict__ Mx, float* __restrict__ Sm, int n)
{
    int i = blockIdx.x * blockDim.x + threadIdx.x;
    if (i < n) { Mx[i] = __int_as_float(0xff800000); Sm[i] = 0.f; }
}

// ---------------- launcher ----------------
extern "C" void kernel_launch(void* const* d_in, const int* in_sizes, int n_in,
                              void* d_out, int out_size)
{
    const int* tok_stmt = (const int*)d_in[0];
    const int* tok_func = (const int*)d_in[1];
    const int* esrc[3] = {(const int*)d_in[2], (const int*)d_in[4], (const int*)d_in[6]};
    const int* edst[3] = {(const int*)d_in[3], (const int*)d_in[5], (const int*)d_in[7]};
    const float* emb   = (const float*)d_in[8];
    const float* lin_w = (const float*)d_in[9];
    const float* lin_b = (const float*)d_in[10];
    const float* kw = (const float*)d_in[11];
    const float* kb = (const float*)d_in[12];
    const float* qw = (const float*)d_in[13];
    const float* qb = (const float*)d_in[14];
    const float* vw = (const float*)d_in[15];
    const float* vb = (const float*)d_in[16];
    const float* aw = (const float*)d_in[17];
    const float* ab = (const float*)d_in[18];
    const float* skip = (const float*)d_in[19];
    const float* a_rel = (const float*)d_in[20];
    const float* m_rel = (const float*)d_in[21];
    const float* p_rel = (const float*)d_in[22];
    float* out = (float*)d_out;

    float *XA, *XB, *Q, *AGG, *KR0, *VR0, *KR1, *VR1, *KR2, *VR2, *LG, *Mx, *Sm;
    float *WK, *WV, *BK, *BV;
    uint32_t *WTH, *WTL;
    cudaGetSymbolAddress((void**)&XA, g_XA);
    cudaGetSymbolAddress((void**)&XB, g_XB);
    cudaGetSymbolAddress((void**)&Q,  g_Q);
    cudaGetSymbolAddress((void**)&AGG, g_AGG);
    cudaGetSymbolAddress((void**)&KR0, g_KR0);
    cudaGetSymbolAddress((void**)&VR0, g_VR0);
    cudaGetSymbolAddress((void**)&KR1, g_KR1);
    cudaGetSymbolAddress((void**)&VR1, g_VR1);
    cudaGetSymbolAddress((void**)&KR2, g_KR2);
    cudaGetSymbolAddress((void**)&VR2, g_VR2);
    cudaGetSymbolAddress((void**)&LG, g_LG);
    cudaGetSymbolAddress((void**)&Mx, g_M);
    cudaGetSymbolAddress((void**)&Sm, g_S);
    cudaGetSymbolAddress((void**)&WK, g_WK);
    cudaGetSymbolAddress((void**)&WV, g_WV);
    cudaGetSymbolAddress((void**)&BK, g_BK);
    cudaGetSymbolAddress((void**)&BV, g_BV);
    cudaGetSymbolAddress((void**)&WTH, g_WTH);
    cudaGetSymbolAddress((void**)&WTL, g_WTL);

    cudaFuncSetAttribute(gemm_mma_kernel, cudaFuncAttributeMaxDynamicSharedMemorySize, SMEM_GM);
    cudaFuncSetAttribute(gemm_mma_multi_kernel, cudaFuncAttributeMaxDynamicSharedMemorySize, SMEM_GM);

    const int Nt[2] = {NSTMT, NFUNC};
    const size_t base[2] = {0, (size_t)NSTMT * CC};

    // ---- fold rel into K/V weights, then pre-convert ALL weights to bf16 hi/lo ----
    combine_kernel<<<NLAYER * 3 * 2, 256>>>(kw, kb, vw, vb, a_rel, m_rel, WK, BK, WV, BV);
    {
        WSrc s;
        for (int t = 0; t < 2; t++) s.w[t] = lin_w + (size_t)t * CC * CC;
        for (int i = 0; i < 4; i++) s.w[2 + i] = qw + (size_t)i * CC * CC;
        for (int i = 0; i < 4; i++) s.w[6 + i] = aw + (size_t)i * CC * CC;
        for (int i = 0; i < 6; i++) s.w[10 + i] = WK + (size_t)i * CC * CC;
        for (int i = 0; i < 6; i++) s.w[16 + i] = WV + (size_t)i * CC * CC;
        wconv_kernel<<<NMAT, 256>>>(s, WTH, WTL);
    }

    // ---- encoder ----
    encode_kernel<<<(NSTMT + 7) / 8, 256>>>(tok_stmt, emb, AGG, NSTMT);
    encode_kernel<<<(NFUNC + 7) / 8, 256>>>(tok_func, emb, AGG + base[1], NFUNC);
    for (int t = 0; t < 2; t++) {
        int g = (Nt[t] + 127) / 128;
        gemm_mma_kernel<<<g, GT, SMEM_GM>>>(
            AGG + base[t], WTH, WTL, t, lin_b + (size_t)t * CC,
            XA + base[t], Nt[t], 1, nullptr, nullptr);
    }

    float* Xcur = XA;
    float* Xnext = XB;

    float* KRr[3] = {KR0, KR1, KR2};
    float* VRr[3] = {VR0, VR1, VR2};

    for (int l = 0; l < NLAYER; l++) {
        // stmt: Q + (KR0, VR0, KR1, VR1) in one multi-GEMM
        {
            MOuts o;
            o.mat[0] = 2 + l * 2 + 0;  o.B[0] = qb + (size_t)(l * 2 + 0) * CC; o.C[0] = Q;
            o.mat[1] = 10 + l * 3 + 0; o.B[1] = BK + (size_t)(l * 3 + 0) * CC; o.C[1] = KR0;
            o.mat[2] = 16 + l * 3 + 0; o.B[2] = BV + (size_t)(l * 3 + 0) * CC; o.C[2] = VR0;
            o.mat[3] = 10 + l * 3 + 1; o.B[3] = BK + (size_t)(l * 3 + 1) * CC; o.C[3] = KR1;
            o.mat[4] = 16 + l * 3 + 1; o.B[4] = BV + (size_t)(l * 3 + 1) * CC; o.C[4] = VR1;
            gemm_mma_multi_kernel<<<(NSTMT + 127) / 128, GT, SMEM_GM>>>(Xcur, WTH, WTL, NSTMT, 5, o);
        }
        // func: Q + (KR2, VR2)
        {
            MOuts o;
            o.mat[0] = 2 + l * 2 + 1;  o.B[0] = qb + (size_t)(l * 2 + 1) * CC; o.C[0] = Q + base[1];
            o.mat[1] = 10 + l * 3 + 2; o.B[1] = BK + (size_t)(l * 3 + 2) * CC; o.C[1] = KR2;
            o.mat[2] = 16 + l * 3 + 2; o.B[2] = BV + (size_t)(l * 3 + 2) * CC; o.C[2] = VR2;
            o.mat[3] = o.mat[0]; o.B[3] = o.B[0]; o.C[3] = Q + base[1];
            o.mat[4] = o.mat[0]; o.B[4] = o.B[0]; o.C[4] = Q + base[1];
            gemm_mma_multi_kernel<<<(NFUNC + 127) / 128, GT, SMEM_GM>>>(Xcur + base[1], WTH, WTL, NFUNC, 3, o);
        }
        cudaMemsetAsync(AGG, 0, (size_t)NTOT * CC * sizeof(float));

        // edge phase: all 3 relations in batched launches
        EdgeCtx c;
        for (int r = 0; r < 3; r++) {
            int dt = (r == 1) ? 1 : 0;
            c.src[r] = esrc[r]; c.dst[r] = edst[r];
            c.Qd[r] = Q + base[dt];
            c.KR[r] = KRr[r]; c.VR[r] = VRr[r];
            c.prel[r] = p_rel + (size_t)(l * 3 + r) * HH;
            c.LG[r] = LG + (size_t)r * EE * HH;
            c.Mx[r] = Mx + (size_t)r * NSTMT * HH;
            c.Sm[r] = Sm + (size_t)r * NSTMT * HH;
            c.AGG[r] = AGG + base[dt];
        }
        init_ms_kernel<<<(3 * NSTMT * HH + 255) / 256, 256>>>(Mx, Sm, 3 * NSTMT * HH);
        logits3_kernel<<<(3 * EE + 7) / 8, 256>>>(c, EE);
        expsum3_kernel<<<(3 * EE * HH + 255) / 256, 256>>>(c, EE);
        scatter3_kernel<<<(3 * EE + 7) / 8, 256>>>(c, EE);

        // output: fused gelu(A) -> proj -> gated skip epilogue
        float* gate_out = (l == NLAYER - 1) ? out : Xnext;
        for (int t = 0; t < 2; t++) {
            int g = (Nt[t] + 127) / 128;
            gemm_mma_kernel<<<g, GT, SMEM_GM>>>(
                AGG + base[t], WTH, WTL, 6 + l * 2 + t, ab + (size_t)(l * 2 + t) * CC,
                gate_out + base[t], Nt[t], 2,
                Xcur + base[t], skip + (size_t)(l * 2 + t));
        }
        float* tmp = Xcur; Xcur = Xnext; Xnext = tmp;
    }
}

// round 13
// speedup vs baseline: 1.0839x; 1.0839x over previous
#include <cuda_runtime.h>
#include <cuda_bf16.h>
#include <math.h>
#include <stdint.h>

#define NSTMT 100000
#define NFUNC 50000
#define NTOT  150000
#define TT 16
#define CC 128
#define HH 8
#define DD 16
#define NLAYER 2
#define EE 200000
#define KPAD 136          // bf16 units per smem row
#define NMAT 22
#define WTU 8192          // u32 per transposed-bf16 matrix (128 n x 64 k-pairs)

// ---------------- scratch (static device globals; no allocation) ----------------
__device__ float g_XA[(size_t)NTOT * CC];
__device__ float g_XB[(size_t)NTOT * CC];
__device__ float g_Q [(size_t)NTOT * CC];
__device__ float g_AGG[(size_t)NTOT * CC];
__device__ float g_KR0[(size_t)NSTMT * CC];
__device__ float g_VR0[(size_t)NSTMT * CC];
__device__ float g_KR1[(size_t)NSTMT * CC];
__device__ float g_VR1[(size_t)NSTMT * CC];
__device__ float g_KR2[(size_t)NFUNC * CC];
__device__ float g_VR2[(size_t)NFUNC * CC];
__device__ float g_LG[(size_t)3 * EE * HH];
__device__ float g_S [(size_t)3 * NSTMT * HH];
// combined rel-folded weights/biases
__device__ float g_WK[(size_t)NLAYER * 3 * CC * CC];
__device__ float g_WV[(size_t)NLAYER * 3 * CC * CC];
__device__ float g_BK[(size_t)NLAYER * 3 * CC];
__device__ float g_BV[(size_t)NLAYER * 3 * CC];
// transposed bf16 hi/lo weights: [mat][n][64 u32]
__device__ uint32_t g_WTH[(size_t)NMAT * WTU];
__device__ uint32_t g_WTL[(size_t)NMAT * WTU];

// ---------------- helpers ----------------
__device__ __forceinline__ void redAdd4(float* p, float4 v) {
    asm volatile("red.global.add.v4.f32 [%0], {%1, %2, %3, %4};"
                 :: "l"(p), "f"(v.x), "f"(v.y), "f"(v.z), "f"(v.w) : "memory");
}

__device__ __forceinline__ float gelu1(float v) {
    float c = 0.7978845608028654f * (v + 0.044715f * v * v * v);
    return 0.5f * v * (1.0f + tanhf(c));
}

__device__ __forceinline__ uint32_t bf2pack(float a, float b) {
    __nv_bfloat162 t = __floats2bfloat162_rn(a, b);
    return *reinterpret_cast<uint32_t*>(&t);
}

__device__ __forceinline__ void mma16816(float* c, uint32_t a0, uint32_t a1, uint32_t a2, uint32_t a3,
                                         uint32_t b0, uint32_t b1) {
    asm volatile(
        "mma.sync.aligned.m16n8k16.row.col.f32.bf16.bf16.f32 "
        "{%0,%1,%2,%3}, {%4,%5,%6,%7}, {%8,%9}, {%0,%1,%2,%3};"
        : "+f"(c[0]), "+f"(c[1]), "+f"(c[2]), "+f"(c[3])
        : "r"(a0), "r"(a1), "r"(a2), "r"(a3), "r"(b0), "r"(b1));
}

// ---------------- weight combine: W' = W @ blockdiag(rel) ----------------
__global__ void combine_kernel(const float* __restrict__ kw, const float* __restrict__ kb,
                               const float* __restrict__ vw, const float* __restrict__ vb,
                               const float* __restrict__ a_rel, const float* __restrict__ m_rel,
                               float* __restrict__ WK, float* __restrict__ BK,
                               float* __restrict__ WV, float* __restrict__ BV)
{
    int b = blockIdx.x;                    // l*6 + r*2 + kind
    int l = b / 6, rr = (b % 6) >> 1, kind = b & 1;
    int st = (rr == 2) ? 1 : 0;
    const float* Wsrc = (kind ? vw : kw) + (size_t)(l * 2 + st) * CC * CC;
    const float* bsrc = (kind ? vb : kb) + (size_t)(l * 2 + st) * CC;
    const float* rel  = (kind ? m_rel : a_rel) + (size_t)(l * 3 + rr) * HH * DD * DD;
    float* Wdst = (kind ? WV : WK) + (size_t)(l * 3 + rr) * CC * CC;
    float* bdst = (kind ? BV : BK) + (size_t)(l * 3 + rr) * CC;

    __shared__ float srel[HH * DD * DD];
    for (int i = threadIdx.x; i < HH * DD * DD; i += blockDim.x) srel[i] = rel[i];
    __syncthreads();

    for (int idx = threadIdx.x; idx < CC * CC; idx += blockDim.x) {
        int j = idx >> 7, c = idx & 127;
        int h = c >> 4, e = c & 15;
        float s = 0.f;
#pragma unroll
        for (int d = 0; d < DD; d++)
            s = fmaf(__ldg(Wsrc + j * CC + h * DD + d), srel[h * DD * DD + d * DD + e], s);
        Wdst[idx] = s;
    }
    if (threadIdx.x < CC) {
        int c = threadIdx.x, h = c >> 4, e = c & 15;
        float s = 0.f;
#pragma unroll
        for (int d = 0; d < DD; d++)
            s = fmaf(__ldg(bsrc + h * DD + d), srel[h * DD * DD + d * DD + e], s);
        bdst[c] = s;
    }
}

// ---------------- one-time: W -> transposed bf16 hi/lo [n][64 u32] ----------------
struct WSrc { const float* w[NMAT]; };

__global__ void wconv_kernel(WSrc s, uint32_t* __restrict__ WTH, uint32_t* __restrict__ WTL)
{
    int mat = blockIdx.x;
    const float* W = s.w[mat];
    int tid = threadIdx.x;
    int n = tid >> 1;
    int k0 = (tid & 1) * 32;
    uint32_t* dh = WTH + (size_t)mat * WTU + n * 64;
    uint32_t* dl = WTL + (size_t)mat * WTU + n * 64;
#pragma unroll 4
    for (int j = 0; j < 32; j++) {
        int kp = k0 + j;
        float w0 = __ldg(W + (size_t)(2 * kp) * CC + n);
        float w1 = __ldg(W + (size_t)(2 * kp + 1) * CC + n);
        float h0 = __bfloat162float(__float2bfloat16_rn(w0));
        float h1 = __bfloat162float(__float2bfloat16_rn(w1));
        dh[kp] = bf2pack(h0, h1);
        dl[kp] = bf2pack(w0 - h0, w1 - h1);
    }
}

// ---------------- encoder: gather + mean + relu ----------------
__global__ void encode_kernel(const int* __restrict__ tok, const float* __restrict__ emb,
                              float* __restrict__ out, int n)
{
    int node = blockIdx.x * (blockDim.x >> 5) + (threadIdx.x >> 5);
    int lane = threadIdx.x & 31;
    if (node >= n) return;
    const int* tk = tok + (size_t)node * TT;
    float4 acc = make_float4(0.f, 0.f, 0.f, 0.f);
#pragma unroll
    for (int t = 0; t < TT; t++) {
        int id = __ldg(tk + t);
        float4 v = __ldg((const float4*)(emb + (size_t)id * CC) + lane);
        acc.x += v.x; acc.y += v.y; acc.z += v.z; acc.w += v.w;
    }
    const float s = 1.0f / TT;
    acc.x = fmaxf(acc.x * s, 0.f); acc.y = fmaxf(acc.y * s, 0.f);
    acc.z = fmaxf(acc.z * s, 0.f); acc.w = fmaxf(acc.w * s, 0.f);
    ((float4*)(out + (size_t)node * CC))[lane] = acc;
}

// ================= HMMA GEMM core (hi/lo split bf16; W pre-converted) =================
#define SMEM_GM (4 * 128 * KPAD * 2)

__device__ __forceinline__ void load_W(const uint32_t* __restrict__ WTHm,
                                       const uint32_t* __restrict__ WTLm,
                                       uint32_t* WH, uint32_t* WL, int tid)
{
#pragma unroll
    for (int i = 0; i < 8; i++) {
        int u4 = tid + i * 256;           // 0..2047
        int n = u4 >> 4, q = u4 & 15;
        uint4 h = __ldg((const uint4*)WTHm + u4);
        uint4 l = __ldg((const uint4*)WTLm + u4);
        *(uint4*)(WH + n * (KPAD / 2) + q * 4) = h;
        *(uint4*)(WL + n * (KPAD / 2) + q * 4) = l;
    }
}

__device__ __forceinline__ void convert_A(const float* __restrict__ A, uint32_t* AH, uint32_t* AL,
                                          int r0, int M, int tid, bool dogelu)
{
#pragma unroll
    for (int i = 0; i < 8; i++) {
        int c = tid + i * 256;
        int r = c >> 4, kc = c & 15;
        float x[8];
        if (r0 + r < M) {
            const float4* ap = (const float4*)(A + (size_t)(r0 + r) * CC + kc * 8);
            float4 v0 = __ldg(ap), v1 = __ldg(ap + 1);
            x[0] = v0.x; x[1] = v0.y; x[2] = v0.z; x[3] = v0.w;
            x[4] = v1.x; x[5] = v1.y; x[6] = v1.z; x[7] = v1.w;
            if (dogelu) {
#pragma unroll
                for (int j = 0; j < 8; j++) x[j] = gelu1(x[j]);
            }
        } else {
#pragma unroll
            for (int j = 0; j < 8; j++) x[j] = 0.f;
        }
        int base = r * (KPAD / 2) + kc * 4;
#pragma unroll
        for (int p = 0; p < 4; p++) {
            float a0 = x[2 * p], a1 = x[2 * p + 1];
            float h0 = __bfloat162float(__float2bfloat16_rn(a0));
            float h1 = __bfloat162float(__float2bfloat16_rn(a1));
            AH[base + p] = bf2pack(h0, h1);
            AL[base + p] = bf2pack(a0 - h0, a1 - h1);
        }
    }
}

// 3-pass split MMA: cfr += Ahi*Whi + Ahi*Wlo + Alo*Whi
__device__ __forceinline__ void mma_core(const uint32_t* AH, const uint32_t* AL,
                                         const uint32_t* WH, const uint32_t* WL,
                                         int wm, int wn, int gr, int qp, float cfr[4][4][4])
{
#pragma unroll
    for (int i = 0; i < 4; i++)
#pragma unroll
        for (int j = 0; j < 4; j++)
#pragma unroll
            for (int q = 0; q < 4; q++) cfr[i][j][q] = 0.f;
#pragma unroll
    for (int p = 0; p < 3; p++) {
        const uint32_t* As = (p < 2) ? AH : AL;
        const uint32_t* Ws = (p == 1) ? WL : WH;
#pragma unroll
        for (int k16 = 0; k16 < 8; k16++) {
            int kb = k16 * 8 + qp;
            uint32_t b[4][2];
#pragma unroll
            for (int nt = 0; nt < 4; nt++) {
                int n = wn + nt * 8 + gr;
                b[nt][0] = Ws[n * (KPAD / 2) + kb];
                b[nt][1] = Ws[n * (KPAD / 2) + kb + 4];
            }
#pragma unroll
            for (int mt = 0; mt < 4; mt++) {
                int r = wm + mt * 16 + gr;
                uint32_t a0 = As[r * (KPAD / 2) + kb];
                uint32_t a1 = As[(r + 8) * (KPAD / 2) + kb];
                uint32_t a2 = As[r * (KPAD / 2) + kb + 4];
                uint32_t a3 = As[(r + 8) * (KPAD / 2) + kb + 4];
#pragma unroll
                for (int nt = 0; nt < 4; nt++)
                    mma16816(cfr[mt][nt], a0, a1, a2, a3, b[nt][0], b[nt][1]);
            }
        }
    }
}

// ---------------- single-output GEMM (encoder / out-proj with epilogue) ----------------
__global__ __launch_bounds__(256) void gemm_mma_kernel(
    const float* __restrict__ A, const uint32_t* __restrict__ WTH, const uint32_t* __restrict__ WTL,
    int mat, const float* __restrict__ bias, float* __restrict__ C, int M, int flags,
    const float* __restrict__ Xg, const float* __restrict__ skipp)
{
    extern __shared__ __align__(16) char smem[];
    uint32_t* AH = (uint32_t*)smem;
    uint32_t* AL = AH + 128 * (KPAD / 2);
    uint32_t* WH = AL + 128 * (KPAD / 2);
    uint32_t* WL = WH + 128 * (KPAD / 2);
    const int tid = threadIdx.x;
    const int r0 = blockIdx.x * 128;

    convert_A(A, AH, AL, r0, M, tid, (flags & 2) != 0);
    load_W(WTH + (size_t)mat * WTU, WTL + (size_t)mat * WTU, WH, WL, tid);
    __syncthreads();

    const int w = tid >> 5, lane = tid & 31;
    const int wm = (w & 1) * 64, wn = (w >> 1) * 32;
    const int gr = lane >> 2, qp = lane & 3;

    float cfr[4][4][4];
    mma_core(AH, AL, WH, WL, wm, wn, gr, qp, cfr);

    float g = 0.f;
    if (Xg) g = 1.0f / (1.0f + __expf(-__ldg(skipp)));
#pragma unroll
    for (int mt = 0; mt < 4; mt++) {
#pragma unroll
        for (int half = 0; half < 2; half++) {
            int row = r0 + wm + mt * 16 + gr + half * 8;
            if (row >= M) continue;
#pragma unroll
            for (int nt = 0; nt < 4; nt++) {
                int j = wn + nt * 8 + qp * 2;
                float o0 = cfr[mt][nt][half * 2 + 0] + __ldg(bias + j);
                float o1 = cfr[mt][nt][half * 2 + 1] + __ldg(bias + j + 1);
                if (flags & 1) { o0 = fmaxf(o0, 0.f); o1 = fmaxf(o1, 0.f); }
                if (Xg) {
                    const float2 xv = __ldg((const float2*)(Xg + (size_t)row * CC + j));
                    o0 = g * o0 + (1.f - g) * xv.x;
                    o1 = g * o1 + (1.f - g) * xv.y;
                }
                *(float2*)(C + (size_t)row * CC + j) = make_float2(o0, o1);
            }
        }
    }
}

// ---------------- multi-output GEMM: A resident, loop over weight sets ----------
struct MOuts {
    int mat[5];
    const float* B[5];
    float*       C[5];
};

__global__ __launch_bounds__(256) void gemm_mma_multi_kernel(
    const float* __restrict__ A, const uint32_t* __restrict__ WTH, const uint32_t* __restrict__ WTL,
    int M, int nw, MOuts o)
{
    extern __shared__ __align__(16) char smem[];
    uint32_t* AH = (uint32_t*)smem;
    uint32_t* AL = AH + 128 * (KPAD / 2);
    uint32_t* WH = AL + 128 * (KPAD / 2);
    uint32_t* WL = WH + 128 * (KPAD / 2);
    const int tid = threadIdx.x;
    const int r0 = blockIdx.x * 128;

    convert_A(A, AH, AL, r0, M, tid, false);

    const int w = tid >> 5, lane = tid & 31;
    const int wm = (w & 1) * 64, wn = (w >> 1) * 32;
    const int gr = lane >> 2, qp = lane & 3;

    for (int s = 0; s < nw; s++) {
        __syncthreads();               // A stores visible (s=0); prior MMA consumers done (s>0)
        load_W(WTH + (size_t)o.mat[s] * WTU, WTL + (size_t)o.mat[s] * WTU, WH, WL, tid);
        __syncthreads();

        float cfr[4][4][4];
        mma_core(AH, AL, WH, WL, wm, wn, gr, qp, cfr);

        const float* bias = o.B[s];
        float* C = o.C[s];
#pragma unroll
        for (int mt = 0; mt < 4; mt++) {
#pragma unroll
            for (int half = 0; half < 2; half++) {
                int row = r0 + wm + mt * 16 + gr + half * 8;
                if (row >= M) continue;
#pragma unroll
                for (int nt = 0; nt < 4; nt++) {
                    int j = wn + nt * 8 + qp * 2;
                    float o0 = cfr[mt][nt][half * 2 + 0] + __ldg(bias + j);
                    float o1 = cfr[mt][nt][half * 2 + 1] + __ldg(bias + j + 1);
                    *(float2*)(C + (size_t)row * CC + j) = make_float2(o0, o1);
                }
            }
        }
    }
}

// ================= edge phase (3 relations batched; unstabilized softmax) ==========
struct EdgeCtx {
    const int* src[3]; const int* dst[3];
    const float* Qd[3]; const float* KR[3]; const float* VR[3];
    const float* prel[3];
    float* LG[3]; float* Sm[3]; float* AGG[3];
};

// pass 1: logits -> exp -> store ev, accumulate segment sum
__global__ void logits3_kernel(EdgeCtx c, int nE)
{
    int e = blockIdx.x * (blockDim.x >> 5) + (threadIdx.x >> 5);
    if (e >= 3 * nE) return;
    int r = e / nE, ei = e - r * nE;
    int lane = threadIdx.x & 31;
    int s = __ldg(c.src[r] + ei), d = __ldg(c.dst[r] + ei);
    float4 q = __ldg((const float4*)(c.Qd[r] + (size_t)d * CC) + lane);
    float4 k = __ldg((const float4*)(c.KR[r] + (size_t)s * CC) + lane);
    float p = q.x * k.x + q.y * k.y + q.z * k.z + q.w * k.w;
    p += __shfl_xor_sync(0xffffffffu, p, 1);
    p += __shfl_xor_sync(0xffffffffu, p, 2);
    if ((lane & 3) == 0) {
        int h = lane >> 2;
        float lg = p * __ldg(c.prel[r] + h) * 0.25f;
        float ev = __expf(fminf(lg, 80.f));
        c.LG[r][(size_t)ei * HH + h] = ev;
        atomicAdd(c.Sm[r] + (size_t)d * HH + h, ev);
    }
}

// pass 2: alpha = ev / sum; scatter alpha * v
__global__ void scatter3_kernel(EdgeCtx c, int nE)
{
    int e = blockIdx.x * (blockDim.x >> 5) + (threadIdx.x >> 5);
    if (e >= 3 * nE) return;
    int r = e / nE, ei = e - r * nE;
    int lane = threadIdx.x & 31;
    int h = lane >> 2;
    int s = __ldg(c.src[r] + ei), d = __ldg(c.dst[r] + ei);
    float a = __ldg(c.LG[r] + (size_t)ei * HH + h) /
              (__ldg(c.Sm[r] + (size_t)d * HH + h) + 1e-16f);
    float4 v = __ldg((const float4*)(c.VR[r] + (size_t)s * CC) + lane);
    redAdd4((float*)((float4*)(c.AGG[r] + (size_t)d * CC) + lane),
            make_float4(v.x * a, v.y * a, v.z * a, v.w * a));
}

// ---------------- launcher ----------------
extern "C" void kernel_launch(void* const* d_in, const int* in_sizes, int n_in,
                              void* d_out, int out_size)
{
    const int* tok_stmt = (const int*)d_in[0];
    const int* tok_func = (const int*)d_in[1];
    const int* esrc[3] = {(const int*)d_in[2], (const int*)d_in[4], (const int*)d_in[6]};
    const int* edst[3] = {(const int*)d_in[3], (const int*)d_in[5], (const int*)d_in[7]};
    const float* emb   = (const float*)d_in[8];
    const float* lin_w = (const float*)d_in[9];
    const float* lin_b = (const float*)d_in[10];
    const float* kw = (const float*)d_in[11];
    const float* kb = (const float*)d_in[12];
    const float* qw = (const float*)d_in[13];
    const float* qb = (const float*)d_in[14];
    const float* vw = (const float*)d_in[15];
    const float* vb = (const float*)d_in[16];
    const float* aw = (const float*)d_in[17];
    const float* ab = (const float*)d_in[18];
    const float* skip = (const float*)d_in[19];
    const float* a_rel = (const float*)d_in[20];
    const float* m_rel = (const float*)d_in[21];
    const float* p_rel = (const float*)d_in[22];
    float* out = (float*)d_out;

    float *XA, *XB, *Q, *AGG, *KR0, *VR0, *KR1, *VR1, *KR2, *VR2, *LG, *Sm;
    float *WK, *WV, *BK, *BV;
    uint32_t *WTH, *WTL;
    cudaGetSymbolAddress((void**)&XA, g_XA);
    cudaGetSymbolAddress((void**)&XB, g_XB);
    cudaGetSymbolAddress((void**)&Q,  g_Q);
    cudaGetSymbolAddress((void**)&AGG, g_AGG);
    cudaGetSymbolAddress((void**)&KR0, g_KR0);
    cudaGetSymbolAddress((void**)&VR0, g_VR0);
    cudaGetSymbolAddress((void**)&KR1, g_KR1);
    cudaGetSymbolAddress((void**)&VR1, g_VR1);
    cudaGetSymbolAddress((void**)&KR2, g_KR2);
    cudaGetSymbolAddress((void**)&VR2, g_VR2);
    cudaGetSymbolAddress((void**)&LG, g_LG);
    cudaGetSymbolAddress((void**)&Sm, g_S);
    cudaGetSymbolAddress((void**)&WK, g_WK);
    cudaGetSymbolAddress((void**)&WV, g_WV);
    cudaGetSymbolAddress((void**)&BK, g_BK);
    cudaGetSymbolAddress((void**)&BV, g_BV);
    cudaGetSymbolAddress((void**)&WTH, g_WTH);
    cudaGetSymbolAddress((void**)&WTL, g_WTL);

    cudaFuncSetAttribute(gemm_mma_kernel, cudaFuncAttributeMaxDynamicSharedMemorySize, SMEM_GM);
    cudaFuncSetAttribute(gemm_mma_multi_kernel, cudaFuncAttributeMaxDynamicSharedMemorySize, SMEM_GM);

    const int Nt[2] = {NSTMT, NFUNC};
    const size_t base[2] = {0, (size_t)NSTMT * CC};

    // ---- fold rel into K/V weights, then pre-convert ALL weights to bf16 hi/lo ----
    combine_kernel<<<NLAYER * 3 * 2, 256>>>(kw, kb, vw, vb, a_rel, m_rel, WK, BK, WV, BV);
    {
        WSrc s;
        for (int t = 0; t < 2; t++) s.w[t] = lin_w + (size_t)t * CC * CC;
        for (int i = 0; i < 4; i++) s.w[2 + i] = qw + (size_t)i * CC * CC;
        for (int i = 0; i < 4; i++) s.w[6 + i] = aw + (size_t)i * CC * CC;
        for (int i = 0; i < 6; i++) s.w[10 + i] = WK + (size_t)i * CC * CC;
        for (int i = 0; i < 6; i++) s.w[16 + i] = WV + (size_t)i * CC * CC;
        wconv_kernel<<<NMAT, 256>>>(s, WTH, WTL);
    }

    // ---- encoder ----
    encode_kernel<<<(NSTMT + 7) / 8, 256>>>(tok_stmt, emb, AGG, NSTMT);
    encode_kernel<<<(NFUNC + 7) / 8, 256>>>(tok_func, emb, AGG + base[1], NFUNC);
    for (int t = 0; t < 2; t++) {
        int g = (Nt[t] + 127) / 128;
        gemm_mma_kernel<<<g, 256, SMEM_GM>>>(
            AGG + base[t], WTH, WTL, t, lin_b + (size_t)t * CC,
            XA + base[t], Nt[t], 1, nullptr, nullptr);
    }

    float* Xcur = XA;
    float* Xnext = XB;

    float* KRr[3] = {KR0, KR1, KR2};
    float* VRr[3] = {VR0, VR1, VR2};

    for (int l = 0; l < NLAYER; l++) {
        // stmt: Q + (KR0, VR0, KR1, VR1) in one multi-GEMM
        {
            MOuts o;
            o.mat[0] = 2 + l * 2 + 0;  o.B[0] = qb + (size_t)(l * 2 + 0) * CC; o.C[0] = Q;
            o.mat[1] = 10 + l * 3 + 0; o.B[1] = BK + (size_t)(l * 3 + 0) * CC; o.C[1] = KR0;
            o.mat[2] = 16 + l * 3 + 0; o.B[2] = BV + (size_t)(l * 3 + 0) * CC; o.C[2] = VR0;
            o.mat[3] = 10 + l * 3 + 1; o.B[3] = BK + (size_t)(l * 3 + 1) * CC; o.C[3] = KR1;
            o.mat[4] = 16 + l * 3 + 1; o.B[4] = BV + (size_t)(l * 3 + 1) * CC; o.C[4] = VR1;
            gemm_mma_multi_kernel<<<(NSTMT + 127) / 128, 256, SMEM_GM>>>(Xcur, WTH, WTL, NSTMT, 5, o);
        }
        // func: Q + (KR2, VR2)
        {
            MOuts o;
            o.mat[0] = 2 + l * 2 + 1;  o.B[0] = qb + (size_t)(l * 2 + 1) * CC; o.C[0] = Q + base[1];
            o.mat[1] = 10 + l * 3 + 2; o.B[1] = BK + (size_t)(l * 3 + 2) * CC; o.C[1] = KR2;
            o.mat[2] = 16 + l * 3 + 2; o.B[2] = BV + (size_t)(l * 3 + 2) * CC; o.C[2] = VR2;
            o.mat[3] = o.mat[0]; o.B[3] = o.B[0]; o.C[3] = Q + base[1];
            o.mat[4] = o.mat[0]; o.B[4] = o.B[0]; o.C[4] = Q + base[1];
            gemm_mma_multi_kernel<<<(NFUNC + 127) / 128, 256, SMEM_GM>>>(Xcur + base[1], WTH, WTL, NFUNC, 3, o);
        }
        cudaMemsetAsync(AGG, 0, (size_t)NTOT * CC * sizeof(float));
        cudaMemsetAsync(Sm, 0, (size_t)3 * NSTMT * HH * sizeof(float));

        // edge phase: all 3 relations in batched launches (unstabilized softmax)
        EdgeCtx c;
        for (int r = 0; r < 3; r++) {
            int dt = (r == 1) ? 1 : 0;
            c.src[r] = esrc[r]; c.dst[r] = edst[r];
            c.Qd[r] = Q + base[dt];
            c.KR[r] = KRr[r]; c.VR[r] = VRr[r];
            c.prel[r] = p_rel + (size_t)(l * 3 + r) * HH;
            c.LG[r] = LG + (size_t)r * EE * HH;
            c.Sm[r] = Sm + (size_t)r * NSTMT * HH;
            c.AGG[r] = AGG + base[dt];
        }
        logits3_kernel<<<(3 * EE + 7) / 8, 256>>>(c, EE);
        scatter3_kernel<<<(3 * EE + 7) / 8, 256>>>(c, EE);

        // output: fused gelu(A) -> proj -> gated skip epilogue
        float* gate_out = (l == NLAYER - 1) ? out : Xnext;
        for (int t = 0; t < 2; t++) {
            int g = (Nt[t] + 127) / 128;
            gemm_mma_kernel<<<g, 256, SMEM_GM>>>(
                AGG + base[t], WTH, WTL, 6 + l * 2 + t, ab + (size_t)(l * 2 + t) * CC,
                gate_out + base[t], Nt[t], 2,
                Xcur + base[t], skip + (size_t)(l * 2 + t));
        }
        float* tmp = Xcur; Xcur = Xnext; Xnext = tmp;
    }
}

// round 15
// speedup vs baseline: 1.5088x; 1.3921x over previous
#include <cuda_runtime.h>
#include <cuda_bf16.h>
#include <math.h>
#include <stdint.h>

#define NSTMT 100000
#define NFUNC 50000
#define NTOT  150000
#define TT 16
#define CC 128
#define HH 8
#define DD 16
#define NLAYER 2
#define EE 200000
#define KPAD 136          // bf16 units per smem row
#define NMAT 22
#define WTU 8192          // u32 per transposed-bf16 matrix (128 n x 64 k-pairs)

// ---------------- scratch (static device globals; no allocation) ----------------
__device__ float g_XA[(size_t)NTOT * CC];
__device__ float g_XB[(size_t)NTOT * CC];
__device__ float g_Q [(size_t)NTOT * CC];
__device__ float g_AGG[(size_t)NTOT * CC];    // r0 -> stmt part, r1 -> func part
__device__ float g_AGG2[(size_t)NSTMT * CC];  // r2 -> stmt
__device__ float g_KR0[(size_t)NSTMT * CC];
__device__ float g_VR0[(size_t)NSTMT * CC];
__device__ float g_KR1[(size_t)NSTMT * CC];
__device__ float g_VR1[(size_t)NSTMT * CC];
__device__ float g_KR2[(size_t)NFUNC * CC];
__device__ float g_VR2[(size_t)NFUNC * CC];
__device__ float g_S [(size_t)3 * NSTMT * HH];
// combined rel-folded weights/biases
__device__ float g_WK[(size_t)NLAYER * 3 * CC * CC];
__device__ float g_WV[(size_t)NLAYER * 3 * CC * CC];
__device__ float g_BK[(size_t)NLAYER * 3 * CC];
__device__ float g_BV[(size_t)NLAYER * 3 * CC];
// transposed bf16 hi/lo weights: [mat][n][64 u32]
__device__ uint32_t g_WTH[(size_t)NMAT * WTU];
__device__ uint32_t g_WTL[(size_t)NMAT * WTU];

// ---------------- helpers ----------------
__device__ __forceinline__ void redAdd4(float* p, float4 v) {
    asm volatile("red.global.add.v4.f32 [%0], {%1, %2, %3, %4};"
                 :: "l"(p), "f"(v.x), "f"(v.y), "f"(v.z), "f"(v.w) : "memory");
}

__device__ __forceinline__ float gelu1(float v) {
    float c = 0.7978845608028654f * (v + 0.044715f * v * v * v);
    return 0.5f * v * (1.0f + tanhf(c));
}

__device__ __forceinline__ uint32_t bf2pack(float a, float b) {
    __nv_bfloat162 t = __floats2bfloat162_rn(a, b);
    return *reinterpret_cast<uint32_t*>(&t);
}

__device__ __forceinline__ void mma16816(float* c, uint32_t a0, uint32_t a1, uint32_t a2, uint32_t a3,
                                         uint32_t b0, uint32_t b1) {
    asm volatile(
        "mma.sync.aligned.m16n8k16.row.col.f32.bf16.bf16.f32 "
        "{%0,%1,%2,%3}, {%4,%5,%6,%7}, {%8,%9}, {%0,%1,%2,%3};"
        : "+f"(c[0]), "+f"(c[1]), "+f"(c[2]), "+f"(c[3])
        : "r"(a0), "r"(a1), "r"(a2), "r"(a3), "r"(b0), "r"(b1));
}

// ---------------- weight combine: W' = W @ blockdiag(rel) ----------------
__global__ void combine_kernel(const float* __restrict__ kw, const float* __restrict__ kb,
                               const float* __restrict__ vw, const float* __restrict__ vb,
                               const float* __restrict__ a_rel, const float* __restrict__ m_rel,
                               float* __restrict__ WK, float* __restrict__ BK,
                               float* __restrict__ WV, float* __restrict__ BV)
{
    int b = blockIdx.x;                    // l*6 + r*2 + kind
    int l = b / 6, rr = (b % 6) >> 1, kind = b & 1;
    int st = (rr == 2) ? 1 : 0;
    const float* Wsrc = (kind ? vw : kw) + (size_t)(l * 2 + st) * CC * CC;
    const float* bsrc = (kind ? vb : kb) + (size_t)(l * 2 + st) * CC;
    const float* rel  = (kind ? m_rel : a_rel) + (size_t)(l * 3 + rr) * HH * DD * DD;
    float* Wdst = (kind ? WV : WK) + (size_t)(l * 3 + rr) * CC * CC;
    float* bdst = (kind ? BV : BK) + (size_t)(l * 3 + rr) * CC;

    __shared__ float srel[HH * DD * DD];
    for (int i = threadIdx.x; i < HH * DD * DD; i += blockDim.x) srel[i] = rel[i];
    __syncthreads();

    for (int idx = threadIdx.x; idx < CC * CC; idx += blockDim.x) {
        int j = idx >> 7, c = idx & 127;
        int h = c >> 4, e = c & 15;
        float s = 0.f;
#pragma unroll
        for (int d = 0; d < DD; d++)
            s = fmaf(__ldg(Wsrc + j * CC + h * DD + d), srel[h * DD * DD + d * DD + e], s);
        Wdst[idx] = s;
    }
    if (threadIdx.x < CC) {
        int c = threadIdx.x, h = c >> 4, e = c & 15;
        float s = 0.f;
#pragma unroll
        for (int d = 0; d < DD; d++)
            s = fmaf(__ldg(bsrc + h * DD + d), srel[h * DD * DD + d * DD + e], s);
        bdst[c] = s;
    }
}

// ---------------- one-time: W -> transposed bf16 hi/lo [n][64 u32] ----------------
struct WSrc { const float* w[NMAT]; };

__global__ void wconv_kernel(WSrc s, uint32_t* __restrict__ WTH, uint32_t* __restrict__ WTL)
{
    int mat = blockIdx.x;
    const float* W = s.w[mat];
    int tid = threadIdx.x;
    int n = tid >> 1;
    int k0 = (tid & 1) * 32;
    uint32_t* dh = WTH + (size_t)mat * WTU + n * 64;
    uint32_t* dl = WTL + (size_t)mat * WTU + n * 64;
#pragma unroll 4
    for (int j = 0; j < 32; j++) {
        int kp = k0 + j;
        float w0 = __ldg(W + (size_t)(2 * kp) * CC + n);
        float w1 = __ldg(W + (size_t)(2 * kp + 1) * CC + n);
        float h0 = __bfloat162float(__float2bfloat16_rn(w0));
        float h1 = __bfloat162float(__float2bfloat16_rn(w1));
        dh[kp] = bf2pack(h0, h1);
        dl[kp] = bf2pack(w0 - h0, w1 - h1);
    }
}

// ---------------- encoder: gather + mean + relu ----------------
__global__ void encode_kernel(const int* __restrict__ tok, const float* __restrict__ emb,
                              float* __restrict__ out, int n)
{
    int node = blockIdx.x * (blockDim.x >> 5) + (threadIdx.x >> 5);
    int lane = threadIdx.x & 31;
    if (node >= n) return;
    const int* tk = tok + (size_t)node * TT;
    float4 acc = make_float4(0.f, 0.f, 0.f, 0.f);
#pragma unroll
    for (int t = 0; t < TT; t++) {
        int id = __ldg(tk + t);
        float4 v = __ldg((const float4*)(emb + (size_t)id * CC) + lane);
        acc.x += v.x; acc.y += v.y; acc.z += v.z; acc.w += v.w;
    }
    const float s = 1.0f / TT;
    acc.x = fmaxf(acc.x * s, 0.f); acc.y = fmaxf(acc.y * s, 0.f);
    acc.z = fmaxf(acc.z * s, 0.f); acc.w = fmaxf(acc.w * s, 0.f);
    ((float4*)(out + (size_t)node * CC))[lane] = acc;
}

// ================= HMMA GEMM core (hi/lo split bf16; W pre-converted) =================
#define SMEM_GM (4 * 128 * KPAD * 2)

__device__ __forceinline__ void load_W(const uint32_t* __restrict__ WTHm,
                                       const uint32_t* __restrict__ WTLm,
                                       uint32_t* WH, uint32_t* WL, int tid)
{
#pragma unroll
    for (int i = 0; i < 8; i++) {
        int u4 = tid + i * 256;           // 0..2047
        int n = u4 >> 4, q = u4 & 15;
        uint4 h = __ldg((const uint4*)WTHm + u4);
        uint4 l = __ldg((const uint4*)WTLm + u4);
        *(uint4*)(WH + n * (KPAD / 2) + q * 4) = h;
        *(uint4*)(WL + n * (KPAD / 2) + q * 4) = l;
    }
}

// plain A conversion (no normalization); optional gelu
__device__ __forceinline__ void convert_A(const float* __restrict__ A, uint32_t* AH, uint32_t* AL,
                                          int r0, int M, int tid, bool dogelu)
{
#pragma unroll
    for (int i = 0; i < 8; i++) {
        int c = tid + i * 256;
        int r = c >> 4, kc = c & 15;
        float x[8];
        if (r0 + r < M) {
            const float4* ap = (const float4*)(A + (size_t)(r0 + r) * CC + kc * 8);
            float4 v0 = __ldg(ap), v1 = __ldg(ap + 1);
            x[0] = v0.x; x[1] = v0.y; x[2] = v0.z; x[3] = v0.w;
            x[4] = v1.x; x[5] = v1.y; x[6] = v1.z; x[7] = v1.w;
            if (dogelu) {
#pragma unroll
                for (int j = 0; j < 8; j++) x[j] = gelu1(x[j]);
            }
        } else {
#pragma unroll
            for (int j = 0; j < 8; j++) x[j] = 0.f;
        }
        int base = r * (KPAD / 2) + kc * 4;
#pragma unroll
        for (int p = 0; p < 4; p++) {
            float a0 = x[2 * p], a1 = x[2 * p + 1];
            float h0 = __bfloat162float(__float2bfloat16_rn(a0));
            float h1 = __bfloat162float(__float2bfloat16_rn(a1));
            AH[base + p] = bf2pack(h0, h1);
            AL[base + p] = bf2pack(a0 - h0, a1 - h1);
        }
    }
}

// normalized A conversion: x = A/(SmA+eps) [+ A2/(SmA2+eps)], then gelu.
// each 8-channel chunk lies within one head: h = kc >> 1.
__device__ __forceinline__ void convert_A_norm(
    const float* __restrict__ A, const float* __restrict__ A2,
    const float* __restrict__ SmA, const float* __restrict__ SmA2,
    uint32_t* AH, uint32_t* AL, int r0, int M, int tid)
{
#pragma unroll
    for (int i = 0; i < 8; i++) {
        int c = tid + i * 256;
        int r = c >> 4, kc = c & 15;
        float x[8];
        int row = r0 + r;
        if (row < M) {
            int h = kc >> 1;
            float inv = 1.0f / (__ldg(SmA + (size_t)row * HH + h) + 1e-16f);
            const float4* ap = (const float4*)(A + (size_t)row * CC + kc * 8);
            float4 v0 = __ldg(ap), v1 = __ldg(ap + 1);
            x[0] = v0.x * inv; x[1] = v0.y * inv; x[2] = v0.z * inv; x[3] = v0.w * inv;
            x[4] = v1.x * inv; x[5] = v1.y * inv; x[6] = v1.z * inv; x[7] = v1.w * inv;
            if (A2) {
                float inv2 = 1.0f / (__ldg(SmA2 + (size_t)row * HH + h) + 1e-16f);
                const float4* ap2 = (const float4*)(A2 + (size_t)row * CC + kc * 8);
                float4 u0 = __ldg(ap2), u1 = __ldg(ap2 + 1);
                x[0] += u0.x * inv2; x[1] += u0.y * inv2; x[2] += u0.z * inv2; x[3] += u0.w * inv2;
                x[4] += u1.x * inv2; x[5] += u1.y * inv2; x[6] += u1.z * inv2; x[7] += u1.w * inv2;
            }
#pragma unroll
            for (int j = 0; j < 8; j++) x[j] = gelu1(x[j]);
        } else {
#pragma unroll
            for (int j = 0; j < 8; j++) x[j] = 0.f;
        }
        int base = r * (KPAD / 2) + kc * 4;
#pragma unroll
        for (int p = 0; p < 4; p++) {
            float a0 = x[2 * p], a1 = x[2 * p + 1];
            float h0 = __bfloat162float(__float2bfloat16_rn(a0));
            float h1 = __bfloat162float(__float2bfloat16_rn(a1));
            AH[base + p] = bf2pack(h0, h1);
            AL[base + p] = bf2pack(a0 - h0, a1 - h1);
        }
    }
}

// 3-pass split MMA: cfr += Ahi*Whi + Ahi*Wlo + Alo*Whi
__device__ __forceinline__ void mma_core(const uint32_t* AH, const uint32_t* AL,
                                         const uint32_t* WH, const uint32_t* WL,
                                         int wm, int wn, int gr, int qp, float cfr[4][4][4])
{
#pragma unroll
    for (int i = 0; i < 4; i++)
#pragma unroll
        for (int j = 0; j < 4; j++)
#pragma unroll
            for (int q = 0; q < 4; q++) cfr[i][j][q] = 0.f;
#pragma unroll
    for (int p = 0; p < 3; p++) {
        const uint32_t* As = (p < 2) ? AH : AL;
        const uint32_t* Ws = (p == 1) ? WL : WH;
#pragma unroll
        for (int k16 = 0; k16 < 8; k16++) {
            int kb = k16 * 8 + qp;
            uint32_t b[4][2];
#pragma unroll
            for (int nt = 0; nt < 4; nt++) {
                int n = wn + nt * 8 + gr;
                b[nt][0] = Ws[n * (KPAD / 2) + kb];
                b[nt][1] = Ws[n * (KPAD / 2) + kb + 4];
            }
#pragma unroll
            for (int mt = 0; mt < 4; mt++) {
                int r = wm + mt * 16 + gr;
                uint32_t a0 = As[r * (KPAD / 2) + kb];
                uint32_t a1 = As[(r + 8) * (KPAD / 2) + kb];
                uint32_t a2 = As[r * (KPAD / 2) + kb + 4];
                uint32_t a3 = As[(r + 8) * (KPAD / 2) + kb + 4];
#pragma unroll
                for (int nt = 0; nt < 4; nt++)
                    mma16816(cfr[mt][nt], a0, a1, a2, a3, b[nt][0], b[nt][1]);
            }
        }
    }
}

// ---------------- single-output GEMM (encoder / out-proj with epilogue) ----------------
// flags: bit0 relu out. Normalization path active when SmA != null (implies gelu).
__global__ __launch_bounds__(256) void gemm_mma_kernel(
    const float* __restrict__ A, const float* __restrict__ A2,
    const float* __restrict__ SmA, const float* __restrict__ SmA2,
    const uint32_t* __restrict__ WTH, const uint32_t* __restrict__ WTL,
    int mat, const float* __restrict__ bias, float* __restrict__ C, int M, int flags,
    const float* __restrict__ Xg, const float* __restrict__ skipp)
{
    extern __shared__ __align__(16) char smem[];
    uint32_t* AH = (uint32_t*)smem;
    uint32_t* AL = AH + 128 * (KPAD / 2);
    uint32_t* WH = AL + 128 * (KPAD / 2);
    uint32_t* WL = WH + 128 * (KPAD / 2);
    const int tid = threadIdx.x;
    const int r0 = blockIdx.x * 128;

    if (SmA) convert_A_norm(A, A2, SmA, SmA2, AH, AL, r0, M, tid);
    else     convert_A(A, AH, AL, r0, M, tid, false);
    load_W(WTH + (size_t)mat * WTU, WTL + (size_t)mat * WTU, WH, WL, tid);
    __syncthreads();

    const int w = tid >> 5, lane = tid & 31;
    const int wm = (w & 1) * 64, wn = (w >> 1) * 32;
    const int gr = lane >> 2, qp = lane & 3;

    float cfr[4][4][4];
    mma_core(AH, AL, WH, WL, wm, wn, gr, qp, cfr);

    float g = 0.f;
    if (Xg) g = 1.0f / (1.0f + __expf(-__ldg(skipp)));
#pragma unroll
    for (int mt = 0; mt < 4; mt++) {
#pragma unroll
        for (int half = 0; half < 2; half++) {
            int row = r0 + wm + mt * 16 + gr + half * 8;
            if (row >= M) continue;
#pragma unroll
            for (int nt = 0; nt < 4; nt++) {
                int j = wn + nt * 8 + qp * 2;
                float o0 = cfr[mt][nt][half * 2 + 0] + __ldg(bias + j);
                float o1 = cfr[mt][nt][half * 2 + 1] + __ldg(bias + j + 1);
                if (flags & 1) { o0 = fmaxf(o0, 0.f); o1 = fmaxf(o1, 0.f); }
                if (Xg) {
                    const float2 xv = __ldg((const float2*)(Xg + (size_t)row * CC + j));
                    o0 = g * o0 + (1.f - g) * xv.x;
                    o1 = g * o1 + (1.f - g) * xv.y;
                }
                *(float2*)(C + (size_t)row * CC + j) = make_float2(o0, o1);
            }
        }
    }
}

// ---------------- multi-output GEMM: A resident, loop over weight sets ----------
struct MOuts {
    int mat[5];
    const float* B[5];
    float*       C[5];
};

__global__ __launch_bounds__(256) void gemm_mma_multi_kernel(
    const float* __restrict__ A, const uint32_t* __restrict__ WTH, const uint32_t* __restrict__ WTL,
    int M, int nw, MOuts o)
{
    extern __shared__ __align__(16) char smem[];
    uint32_t* AH = (uint32_t*)smem;
    uint32_t* AL = AH + 128 * (KPAD / 2);
    uint32_t* WH = AL + 128 * (KPAD / 2);
    uint32_t* WL = WH + 128 * (KPAD / 2);
    const int tid = threadIdx.x;
    const int r0 = blockIdx.x * 128;

    convert_A(A, AH, AL, r0, M, tid, false);

    const int w = tid >> 5, lane = tid & 31;
    const int wm = (w & 1) * 64, wn = (w >> 1) * 32;
    const int gr = lane >> 2, qp = lane & 3;

    for (int s = 0; s < nw; s++) {
        __syncthreads();               // A stores visible (s=0); prior MMA consumers done (s>0)
        load_W(WTH + (size_t)o.mat[s] * WTU, WTL + (size_t)o.mat[s] * WTU, WH, WL, tid);
        __syncthreads();

        float cfr[4][4][4];
        mma_core(AH, AL, WH, WL, wm, wn, gr, qp, cfr);

        const float* bias = o.B[s];
        float* C = o.C[s];
#pragma unroll
        for (int mt = 0; mt < 4; mt++) {
#pragma unroll
            for (int half = 0; half < 2; half++) {
                int row = r0 + wm + mt * 16 + gr + half * 8;
                if (row >= M) continue;
#pragma unroll
                for (int nt = 0; nt < 4; nt++) {
                    int j = wn + nt * 8 + qp * 2;
                    float o0 = cfr[mt][nt][half * 2 + 0] + __ldg(bias + j);
                    float o1 = cfr[mt][nt][half * 2 + 1] + __ldg(bias + j + 1);
                    *(float2*)(C + (size_t)row * CC + j) = make_float2(o0, o1);
                }
            }
        }
    }
}

// ================= fused edge phase (one pass; unnormalized scatter) ==========
struct EdgeCtx {
    const int* src[3]; const int* dst[3];
    const float* Qd[3]; const float* KR[3]; const float* VR[3];
    const float* prel[3];
    float* Sm[3]; float* AGG[3];
};

__global__ void edge_fused_kernel(EdgeCtx c, int nE)
{
    int e = blockIdx.x * (blockDim.x >> 5) + (threadIdx.x >> 5);
    if (e >= 3 * nE) return;
    int r = e / nE, ei = e - r * nE;
    int lane = threadIdx.x & 31;
    int s = __ldg(c.src[r] + ei), d = __ldg(c.dst[r] + ei);
    float4 q = __ldg((const float4*)(c.Qd[r] + (size_t)d * CC) + lane);
    float4 k = __ldg((const float4*)(c.KR[r] + (size_t)s * CC) + lane);
    float p = q.x * k.x + q.y * k.y + q.z * k.z + q.w * k.w;
    p += __shfl_xor_sync(0xffffffffu, p, 1);
    p += __shfl_xor_sync(0xffffffffu, p, 2);
    int h = lane >> 2;
    float lg = p * __ldg(c.prel[r] + h) * 0.25f;
    float ev = __expf(fminf(lg, 80.f));
    if ((lane & 3) == 0) atomicAdd(c.Sm[r] + (size_t)d * HH + h, ev);
    float4 v = __ldg((const float4*)(c.VR[r] + (size_t)s * CC) + lane);
    redAdd4((float*)((float4*)(c.AGG[r] + (size_t)d * CC) + lane),
            make_float4(v.x * ev, v.y * ev, v.z * ev, v.w * ev));
}

// ---------------- launcher ----------------
extern "C" void kernel_launch(void* const* d_in, const int* in_sizes, int n_in,
                              void* d_out, int out_size)
{
    const int* tok_stmt = (const int*)d_in[0];
    const int* tok_func = (const int*)d_in[1];
    const int* esrc[3] = {(const int*)d_in[2], (const int*)d_in[4], (const int*)d_in[6]};
    const int* edst[3] = {(const int*)d_in[3], (const int*)d_in[5], (const int*)d_in[7]};
    const float* emb   = (const float*)d_in[8];
    const float* lin_w = (const float*)d_in[9];
    const float* lin_b = (const float*)d_in[10];
    const float* kw = (const float*)d_in[11];
    const float* kb = (const float*)d_in[12];
    const float* qw = (const float*)d_in[13];
    const float* qb = (const float*)d_in[14];
    const float* vw = (const float*)d_in[15];
    const float* vb = (const float*)d_in[16];
    const float* aw = (const float*)d_in[17];
    const float* ab = (const float*)d_in[18];
    const float* skip = (const float*)d_in[19];
    const float* a_rel = (const float*)d_in[20];
    const float* m_rel = (const float*)d_in[21];
    const float* p_rel = (const float*)d_in[22];
    float* out = (float*)d_out;

    float *XA, *XB, *Q, *AGG, *AGG2, *KR0, *VR0, *KR1, *VR1, *KR2, *VR2, *Sm;
    float *WK, *WV, *BK, *BV;
    uint32_t *WTH, *WTL;
    cudaGetSymbolAddress((void**)&XA, g_XA);
    cudaGetSymbolAddress((void**)&XB, g_XB);
    cudaGetSymbolAddress((void**)&Q,  g_Q);
    cudaGetSymbolAddress((void**)&AGG, g_AGG);
    cudaGetSymbolAddress((void**)&AGG2, g_AGG2);
    cudaGetSymbolAddress((void**)&KR0, g_KR0);
    cudaGetSymbolAddress((void**)&VR0, g_VR0);
    cudaGetSymbolAddress((void**)&KR1, g_KR1);
    cudaGetSymbolAddress((void**)&VR1, g_VR1);
    cudaGetSymbolAddress((void**)&KR2, g_KR2);
    cudaGetSymbolAddress((void**)&VR2, g_VR2);
    cudaGetSymbolAddress((void**)&Sm, g_S);
    cudaGetSymbolAddress((void**)&WK, g_WK);
    cudaGetSymbolAddress((void**)&WV, g_WV);
    cudaGetSymbolAddress((void**)&BK, g_BK);
    cudaGetSymbolAddress((void**)&BV, g_BV);
    cudaGetSymbolAddress((void**)&WTH, g_WTH);
    cudaGetSymbolAddress((void**)&WTL, g_WTL);

    cudaFuncSetAttribute(gemm_mma_kernel, cudaFuncAttributeMaxDynamicSharedMemorySize, SMEM_GM);
    cudaFuncSetAttribute(gemm_mma_multi_kernel, cudaFuncAttributeMaxDynamicSharedMemorySize, SMEM_GM);

    const int Nt[2] = {NSTMT, NFUNC};
    const size_t base[2] = {0, (size_t)NSTMT * CC};

    // ---- fold rel into K/V weights, then pre-convert ALL weights to bf16 hi/lo ----
    combine_kernel<<<NLAYER * 3 * 2, 256>>>(kw, kb, vw, vb, a_rel, m_rel, WK, BK, WV, BV);
    {
        WSrc s;
        for (int t = 0; t < 2; t++) s.w[t] = lin_w + (size_t)t * CC * CC;
        for (int i = 0; i < 4; i++) s.w[2 + i] = qw + (size_t)i * CC * CC;
        for (int i = 0; i < 4; i++) s.w[6 + i] = aw + (size_t)i * CC * CC;
        for (int i = 0; i < 6; i++) s.w[10 + i] = WK + (size_t)i * CC * CC;
        for (int i = 0; i < 6; i++) s.w[16 + i] = WV + (size_t)i * CC * CC;
        wconv_kernel<<<NMAT, 256>>>(s, WTH, WTL);
    }

    // ---- encoder (AGG used as staging; encoder GEMM applies relu) ----
    encode_kernel<<<(NSTMT + 7) / 8, 256>>>(tok_stmt, emb, AGG, NSTMT);
    encode_kernel<<<(NFUNC + 7) / 8, 256>>>(tok_func, emb, AGG + base[1], NFUNC);
    for (int t = 0; t < 2; t++) {
        int g = (Nt[t] + 127) / 128;
        gemm_mma_kernel<<<g, 256, SMEM_GM>>>(
            AGG + base[t], nullptr, nullptr, nullptr, WTH, WTL, t, lin_b + (size_t)t * CC,
            XA + base[t], Nt[t], 1, nullptr, nullptr);
    }

    float* Xcur = XA;
    float* Xnext = XB;

    float* KRr[3] = {KR0, KR1, KR2};
    float* VRr[3] = {VR0, VR1, VR2};

    for (int l = 0; l < NLAYER; l++) {
        // stmt: Q + (KR0, VR0, KR1, VR1) in one multi-GEMM
        {
            MOuts o;
            o.mat[0] = 2 + l * 2 + 0;  o.B[0] = qb + (size_t)(l * 2 + 0) * CC; o.C[0] = Q;
            o.mat[1] = 10 + l * 3 + 0; o.B[1] = BK + (size_t)(l * 3 + 0) * CC; o.C[1] = KR0;
            o.mat[2] = 16 + l * 3 + 0; o.B[2] = BV + (size_t)(l * 3 + 0) * CC; o.C[2] = VR0;
            o.mat[3] = 10 + l * 3 + 1; o.B[3] = BK + (size_t)(l * 3 + 1) * CC; o.C[3] = KR1;
            o.mat[4] = 16 + l * 3 + 1; o.B[4] = BV + (size_t)(l * 3 + 1) * CC; o.C[4] = VR1;
            gemm_mma_multi_kernel<<<(NSTMT + 127) / 128, 256, SMEM_GM>>>(Xcur, WTH, WTL, NSTMT, 5, o);
        }
        // func: Q + (KR2, VR2)
        {
            MOuts o;
            o.mat[0] = 2 + l * 2 + 1;  o.B[0] = qb + (size_t)(l * 2 + 1) * CC; o.C[0] = Q + base[1];
            o.mat[1] = 10 + l * 3 + 2; o.B[1] = BK + (size_t)(l * 3 + 2) * CC; o.C[1] = KR2;
            o.mat[2] = 16 + l * 3 + 2; o.B[2] = BV + (size_t)(l * 3 + 2) * CC; o.C[2] = VR2;
            o.mat[3] = o.mat[0]; o.B[3] = o.B[0]; o.C[3] = Q + base[1];
            o.mat[4] = o.mat[0]; o.B[4] = o.B[0]; o.C[4] = Q + base[1];
            gemm_mma_multi_kernel<<<(NFUNC + 127) / 128, 256, SMEM_GM>>>(Xcur + base[1], WTH, WTL, NFUNC, 3, o);
        }
        cudaMemsetAsync(AGG, 0, (size_t)NTOT * CC * sizeof(float));
        cudaMemsetAsync(AGG2, 0, (size_t)NSTMT * CC * sizeof(float));
        cudaMemsetAsync(Sm, 0, (size_t)3 * NSTMT * HH * sizeof(float));

        // fused edge phase: one pass, unnormalized scatter + per-relation sums
        EdgeCtx c;
        for (int r = 0; r < 3; r++) {
            int dt = (r == 1) ? 1 : 0;
            c.src[r] = esrc[r]; c.dst[r] = edst[r];
            c.Qd[r] = Q + base[dt];
            c.KR[r] = KRr[r]; c.VR[r] = VRr[r];
            c.prel[r] = p_rel + (size_t)(l * 3 + r) * HH;
            c.Sm[r] = Sm + (size_t)r * NSTMT * HH;
        }
        c.AGG[0] = AGG;            // stmt, relation 0
        c.AGG[1] = AGG + base[1];  // func, relation 1
        c.AGG[2] = AGG2;           // stmt, relation 2
        edge_fused_kernel<<<(3 * EE + 7) / 8, 256>>>(c, EE);

        // output: normalize (+combine r0/r2) -> gelu -> proj -> gated skip
        float* gate_out = (l == NLAYER - 1) ? out : Xnext;
        // stmt
        gemm_mma_kernel<<<(NSTMT + 127) / 128, 256, SMEM_GM>>>(
            AGG, AGG2, Sm + 0, Sm + (size_t)2 * NSTMT * HH,
            WTH, WTL, 6 + l * 2 + 0, ab + (size_t)(l * 2 + 0) * CC,
            gate_out, NSTMT, 0, Xcur, skip + (size_t)(l * 2 + 0));
        // func
        gemm_mma_kernel<<<(NFUNC + 127) / 128, 256, SMEM_GM>>>(
            AGG + base[1], nullptr, Sm + (size_t)1 * NSTMT * HH, nullptr,
            WTH, WTL, 6 + l * 2 + 1, ab + (size_t)(l * 2 + 1) * CC,
            gate_out + base[1], NFUNC, 0, Xcur + base[1], skip + (size_t)(l * 2 + 1));
        float* tmp = Xcur; Xcur = Xnext; Xnext = tmp;
    }
}